// round 11
// baseline (speedup 1.0000x reference)
#include <cuda_runtime.h>
#include <cuda_bf16.h>
#include <cstdint>

constexpr int LYR = 5;
constexpr int NN  = 50000;
constexpr int EE  = 600000;
constexpr int DD  = 128;
constexpr int GG  = 256;
constexpr int OO  = 10;
constexpr float BN_EPS = 1e-5f;

__device__ float g_X[NN * DD];
__device__ __nv_bfloat16 g_XB16[NN * DD];   // bf16 mirror of X for msg gathers
__device__ float g_AGGR[NN * DD];
__device__ float g_POOL[(LYR + 1) * GG * DD];
__device__ float g_CNT[GG];
__device__ __nv_bfloat16 g_COMBO[LYR * 512 * DD];
// CSR (rebuilt every launch; edges sorted by dst)
__device__ int  g_DEG[NN];
__device__ int  g_ROWPTR[NN + 1];
__device__ int  g_WPOS[NN];
__device__ int2 g_ESRC[EE];          // {src, combo_code}
// Pre-transposed, split, swizzled weights: [layer][w1/w2][hi/lo][n*128 + swizzled k]
__device__ __align__(16) __nv_bfloat16 g_WT[LYR][2][2][DD * DD];

// ---------------------------------------------------------------------------
// Helpers
// ---------------------------------------------------------------------------
__device__ __forceinline__ uint32_t smem_u32(const void* p) {
    uint32_t a;
    asm("{ .reg .u64 t; cvta.to.shared.u64 t, %1; cvt.u32.u64 %0, t; }" : "=r"(a) : "l"(p));
    return a;
}

__device__ __forceinline__ void red_add_v4(float* addr, float a, float b, float c, float d) {
    asm volatile(
        "{ .reg .u64 p; cvta.to.global.u64 p, %0;\n\t"
        "red.global.add.v4.f32 [p], {%1, %2, %3, %4}; }"
        :: "l"(addr), "f"(a), "f"(b), "f"(c), "f"(d) : "memory");
}
__device__ __forceinline__ void red_add_v2(float* addr, float a, float b) {
    asm volatile(
        "{ .reg .u64 p; cvta.to.global.u64 p, %0;\n\t"
        "red.global.add.v2.f32 [p], {%1, %2}; }"
        :: "l"(addr), "f"(a), "f"(b) : "memory");
}

__device__ __forceinline__ void ldm_x4(uint32_t* r, uint32_t addr) {
    asm volatile("ldmatrix.sync.aligned.m8n8.x4.shared.b16 {%0,%1,%2,%3}, [%4];"
        : "=r"(r[0]), "=r"(r[1]), "=r"(r[2]), "=r"(r[3]) : "r"(addr));
}

#define MMA_BF16(d, a, b0_, b1_) \
    asm volatile("mma.sync.aligned.m16n8k16.row.col.f32.bf16.bf16.f32 " \
        "{%0,%1,%2,%3}, {%4,%5,%6,%7}, {%8,%9}, {%0,%1,%2,%3};" \
        : "+f"((d)[0]), "+f"((d)[1]), "+f"((d)[2]), "+f"((d)[3]) \
        : "r"((a)[0]), "r"((a)[1]), "r"((a)[2]), "r"((a)[3]), "r"(b0_), "r"(b1_))

__device__ __forceinline__ uint32_t pack_hi(float v0, float v1) {
    __nv_bfloat16 h0 = __float2bfloat16(v0), h1 = __float2bfloat16(v1);
    return (uint32_t)__bfloat16_as_ushort(h0) | ((uint32_t)__bfloat16_as_ushort(h1) << 16);
}
__device__ __forceinline__ uint32_t pack_lo(float v0, float v1) {
    __nv_bfloat16 h0 = __float2bfloat16(v0), h1 = __float2bfloat16(v1);
    __nv_bfloat16 l0 = __float2bfloat16(v0 - __bfloat162float(h0));
    __nv_bfloat16 l1 = __float2bfloat16(v1 - __bfloat162float(h1));
    return (uint32_t)__bfloat16_as_ushort(l0) | ((uint32_t)__bfloat16_as_ushort(l1) << 16);
}

// XOR-swizzled byte offset in a 128x128 bf16 tile (rows of 256B, 16B chunks)
__device__ __forceinline__ uint32_t sw_off(int row, int chunk) {
    return (uint32_t)(row * 256 + ((chunk ^ (row & 7)) << 4));
}

// SMEM layout (bytes) — 128-row tile (R9 layout)
constexpr int SM_SC1 = 0;
constexpr int SM_SH1 = 512;
constexpr int SM_SC2 = 1024;
constexpr int SM_SH2 = 1536;
constexpr int SM_AHI = 2048;
constexpr int SM_ALO = SM_AHI + 32768;
constexpr int SM_WHI = SM_ALO + 32768;
constexpr int SM_WLO = SM_WHI + 32768;
constexpr int SM_TOTAL = SM_WLO + 32768;     // 133120 B

// ---------------------------------------------------------------------------
// Setup kernels
// ---------------------------------------------------------------------------
__global__ void zero_pool_kernel() {
    int idx = blockIdx.x * blockDim.x + threadIdx.x;
    if (idx < (LYR + 1) * GG * DD) g_POOL[idx] = 0.f;
    if (idx < GG) g_CNT[idx] = 0.f;
    if (idx < NN) g_DEG[idx] = 0;
}

// Convert input x -> bf16 mirror (one-time; later layers written by fused epilogue)
__global__ void x2b16_kernel(const float* __restrict__ x) {
    int i = blockIdx.x * blockDim.x + threadIdx.x;   // over pairs
    const int npairs = NN * DD / 2;
    if (i < npairs) {
        float2 v = *reinterpret_cast<const float2*>(&x[i * 2]);
        *reinterpret_cast<uint32_t*>(&g_XB16[i * 2]) = pack_hi(v.x, v.y);
    }
}

__global__ void pool0_kernel(const float* __restrict__ x, const int* __restrict__ batch) {
    int idx = blockIdx.x * blockDim.x + threadIdx.x;
    int n = idx >> 5;
    int lane = idx & 31;
    if (n >= NN) return;
    int g = batch[n];
    if (lane == 0) atomicAdd(&g_CNT[g], 1.0f);
    float4 v = *reinterpret_cast<const float4*>(&x[n * DD + lane * 4]);
    red_add_v4(&g_POOL[g * DD + lane * 4], v.x, v.y, v.z, v.w);
}

__global__ void hist_kernel(const int* __restrict__ ei) {
    int e = blockIdx.x * blockDim.x + threadIdx.x;
    if (e < EE) atomicAdd(&g_DEG[ei[EE + e]], 1);
}

__global__ void scan_kernel() {
    __shared__ int part[1024];
    const int t = threadIdx.x;
    const int CH = (NN + 1023) / 1024;
    const int base = t * CH;
    int sum = 0;
    for (int j = 0; j < CH; j++) {
        int i = base + j;
        if (i < NN) sum += g_DEG[i];
    }
    part[t] = sum;
    __syncthreads();
    for (int off = 1; off < 1024; off <<= 1) {
        int v = (t >= off) ? part[t - off] : 0;
        __syncthreads();
        part[t] += v;
        __syncthreads();
    }
    int run = (t == 0) ? 0 : part[t - 1];
    for (int j = 0; j < CH; j++) {
        int i = base + j;
        if (i < NN) {
            g_ROWPTR[i] = run;
            g_WPOS[i] = run;
            run += g_DEG[i];
        }
    }
    if (t == 1023) g_ROWPTR[NN] = run;
}

__global__ void scatter_kernel(const int* __restrict__ ei, const int* __restrict__ eattr) {
    int e = blockIdx.x * blockDim.x + threadIdx.x;
    if (e < EE) {
        int dst = ei[EE + e];
        int pos = atomicAdd(&g_WPOS[dst], 1);
        int2 rec;
        rec.x = ei[e];
        rec.y = eattr[e * 3 + 0] + 8 * eattr[e * 3 + 1] + 64 * eattr[e * 3 + 2];
        g_ESRC[pos] = rec;
    }
}

// All-layer combined bond tables (bf16): grid (512, LYR)
__global__ void combo_kernel(const float* __restrict__ bemb) {
    int c = blockIdx.x, l = blockIdx.y, d = threadIdx.x;
    const float* bl = bemb + (size_t)l * 3 * 8 * DD;
    int a0 = c & 7, a1 = (c >> 3) & 7, a2 = c >> 6;
    float s = bl[a0 * DD + d] + bl[(8 + a1) * DD + d] + bl[(16 + a2) * DD + d];
    g_COMBO[((size_t)l * 512 + c) * DD + d] = __float2bfloat16(s);
}

// Transpose + split + swizzle weights: grid (LYR, 2, 4)
__global__ void prep_w_kernel(const float* __restrict__ w1, const float* __restrict__ w2) {
    int l = blockIdx.x, which = blockIdx.y, part = blockIdx.z;
    const float* W = (which ? w2 : w1) + (size_t)l * DD * DD;
    __nv_bfloat16* dst_hi = g_WT[l][which][0];
    __nv_bfloat16* dst_lo = g_WT[l][which][1];
    const int quarter = DD * DD / 4;
    for (int idx = part * quarter + threadIdx.x; idx < (part + 1) * quarter; idx += blockDim.x) {
        int k = idx >> 7, n = idx & 127;
        float v = W[idx];
        __nv_bfloat16 hi = __float2bfloat16(v);
        __nv_bfloat16 lo = __float2bfloat16(v - __bfloat162float(hi));
        int sidx = n * DD + (((k >> 3) ^ (n & 7)) << 3) + (k & 7);
        dst_hi[sidx] = hi;
        dst_lo[sidx] = lo;
    }
}

// ---------------------------------------------------------------------------
// CSR gather aggregation: AGGR[n] = sum over in-edges relu(xb16[src] + combo)
// One warp per node; register accumulation; plain store (no atomics).
// ---------------------------------------------------------------------------
__global__ void __launch_bounds__(256)
msg_csr_kernel(int layer) {
    const __nv_bfloat16* combo = g_COMBO + (size_t)layer * 512 * DD;
    const int lane = threadIdx.x & 31;
    const int n = blockIdx.x * 8 + (threadIdx.x >> 5);
    if (n >= NN) return;

    const int s = g_ROWPTR[n];
    const int e = g_ROWPTR[n + 1];
    float4 acc = make_float4(0.f, 0.f, 0.f, 0.f);
#pragma unroll 2
    for (int i = s; i < e; i++) {
        int2 ed = g_ESRC[i];   // warp-uniform broadcast
        uint2 cu = *reinterpret_cast<const uint2*>(&combo[(size_t)ed.y * DD + lane * 4]);
        uint2 xu = *reinterpret_cast<const uint2*>(&g_XB16[(size_t)ed.x * DD + lane * 4]);
        float2 c0 = __bfloat1622float2(*reinterpret_cast<__nv_bfloat162*>(&cu.x));
        float2 c1 = __bfloat1622float2(*reinterpret_cast<__nv_bfloat162*>(&cu.y));
        float2 x0 = __bfloat1622float2(*reinterpret_cast<__nv_bfloat162*>(&xu.x));
        float2 x1 = __bfloat1622float2(*reinterpret_cast<__nv_bfloat162*>(&xu.y));
        acc.x += fmaxf(x0.x + c0.x, 0.f);
        acc.y += fmaxf(x0.y + c0.y, 0.f);
        acc.z += fmaxf(x1.x + c1.x, 0.f);
        acc.w += fmaxf(x1.y + c1.y, 0.f);
    }
    *reinterpret_cast<float4*>(&g_AGGR[(size_t)n * DD + lane * 4]) = acc;
}

// ---------------------------------------------------------------------------
// Fused layer kernel (HMMA bf16 split-3x), 128-row tile (R9 version):
//   A = x + AGGR -> smem bf16 hi/lo (swizzled [M][K])
//   pass0: D1 = A @ W1^T; H1 = relu(bn1(D1)) -> smem (overwrites A); load W2
//   pass1: D2 = H1 @ W2^T; Xn = relu(bn2(D2)) -> g_X + g_XB16 + pool atomics
// ---------------------------------------------------------------------------
__global__ void __launch_bounds__(256)
fused_mma_kernel(const float* __restrict__ xext,
                 const int* __restrict__ batch,
                 const float* __restrict__ b1,
                 const float* __restrict__ g1, const float* __restrict__ be1,
                 const float* __restrict__ mu1, const float* __restrict__ v1,
                 const float* __restrict__ b2,
                 const float* __restrict__ g2, const float* __restrict__ be2,
                 const float* __restrict__ mu2, const float* __restrict__ v2,
                 int layer) {
    extern __shared__ char smc[];
    const int tid = threadIdx.x;
    const int lane = tid & 31;
    const int wid = tid >> 5;
    const int wm = wid >> 1;
    const int wn = wid & 1;
    const int m0 = blockIdx.x * 128;
    const float* Ain = xext ? xext : g_X;

    float* s_sc1 = reinterpret_cast<float*>(smc + SM_SC1);
    float* s_sh1 = reinterpret_cast<float*>(smc + SM_SH1);
    float* s_sc2 = reinterpret_cast<float*>(smc + SM_SC2);
    float* s_sh2 = reinterpret_cast<float*>(smc + SM_SH2);

    const uint32_t aHi = smem_u32(smc + SM_AHI);
    const uint32_t aLo = smem_u32(smc + SM_ALO);
    const uint32_t wHi = smem_u32(smc + SM_WHI);
    const uint32_t wLo = smem_u32(smc + SM_WLO);

    if (tid < 128) {
        int c = tid;
        float s1 = g1[c] * rsqrtf(v1[c] + BN_EPS);
        s_sc1[c] = s1;
        s_sh1[c] = be1[c] + (b1[c] - mu1[c]) * s1;
        float s2 = g2[c] * rsqrtf(v2[c] + BN_EPS);
        s_sc2[c] = s2;
        s_sh2[c] = be2[c] + (b2[c] - mu2[c]) * s2;
    }
    {
        const int r = tid >> 1;
        const int h = tid & 1;
        const int m = m0 + r;
#pragma unroll
        for (int q = 0; q < 8; q++) {
            int c0 = h * 64 + q * 8;
            float4 v0 = make_float4(0.f, 0.f, 0.f, 0.f);
            float4 v1f = make_float4(0.f, 0.f, 0.f, 0.f);
            if (m < NN) {
                size_t gi = (size_t)m * DD + c0;
                v0 = *reinterpret_cast<const float4*>(&Ain[gi]);
                v1f = *reinterpret_cast<const float4*>(&Ain[gi + 4]);
                float4 a0 = *reinterpret_cast<const float4*>(&g_AGGR[gi]);
                float4 a1 = *reinterpret_cast<const float4*>(&g_AGGR[gi + 4]);
                v0.x += a0.x; v0.y += a0.y; v0.z += a0.z; v0.w += a0.w;
                v1f.x += a1.x; v1f.y += a1.y; v1f.z += a1.z; v1f.w += a1.w;
            }
            uint32_t off = sw_off(r, h * 8 + q);
            uint4 hi4 = make_uint4(pack_hi(v0.x, v0.y), pack_hi(v0.z, v0.w),
                                   pack_hi(v1f.x, v1f.y), pack_hi(v1f.z, v1f.w));
            uint4 lo4 = make_uint4(pack_lo(v0.x, v0.y), pack_lo(v0.z, v0.w),
                                   pack_lo(v1f.x, v1f.y), pack_lo(v1f.z, v1f.w));
            *reinterpret_cast<uint4*>(smc + SM_AHI + off) = hi4;
            *reinterpret_cast<uint4*>(smc + SM_ALO + off) = lo4;
        }
    }
    {
        const uint4* sh = reinterpret_cast<const uint4*>(g_WT[layer][0][0]);
        const uint4* sl = reinterpret_cast<const uint4*>(g_WT[layer][0][1]);
        uint4* dh = reinterpret_cast<uint4*>(smc + SM_WHI);
        uint4* dl = reinterpret_cast<uint4*>(smc + SM_WLO);
#pragma unroll
        for (int i = 0; i < 8; i++) {
            dh[tid + i * 256] = sh[tid + i * 256];
            dl[tid + i * 256] = sl[tid + i * 256];
        }
    }
    __syncthreads();

    const int lrow = lane & 15;
    const int lhalf = lane >> 4;
    const int ar0 = wm * 32 + lrow;
    const int ar1 = ar0 + 16;
    const int ar0b = ar0 * 256, ar0x = ar0 & 7;
    const int ar1b = ar1 * 256, ar1x = ar1 & 7;
    int brb[4], brx[4];
#pragma unroll
    for (int p = 0; p < 4; p++) {
        int nr = wn * 64 + p * 16 + lrow;
        brb[p] = nr * 256;
        brx[p] = nr & 7;
    }

    float acc[64];
#pragma unroll
    for (int i = 0; i < 64; i++) acc[i] = 0.f;

    for (int pass = 0; pass < 2; ++pass) {
#pragma unroll
        for (int ks = 0; ks < 8; ks++) {
            const int ch = ks * 2 + lhalf;
            uint32_t a0[4], a1[4];
            ldm_x4(a0, aHi + ar0b + ((uint32_t)(ch ^ ar0x) << 4));
            ldm_x4(a1, aHi + ar1b + ((uint32_t)(ch ^ ar1x) << 4));
            uint32_t bh[4][4], bl[4][4];
#pragma unroll
            for (int p = 0; p < 4; p++) {
                uint32_t o = (uint32_t)(ch ^ brx[p]) << 4;
                ldm_x4(bh[p], wHi + brb[p] + o);
                ldm_x4(bl[p], wLo + brb[p] + o);
            }
#pragma unroll
            for (int p = 0; p < 4; p++) {
                MMA_BF16(acc + (2 * p) * 4,      a0, bh[p][0], bh[p][2]);
                MMA_BF16(acc + (2 * p + 1) * 4,  a0, bh[p][1], bh[p][3]);
                MMA_BF16(acc + 32 + (2 * p) * 4,     a1, bh[p][0], bh[p][2]);
                MMA_BF16(acc + 32 + (2 * p + 1) * 4, a1, bh[p][1], bh[p][3]);
                MMA_BF16(acc + (2 * p) * 4,      a0, bl[p][0], bl[p][2]);
                MMA_BF16(acc + (2 * p + 1) * 4,  a0, bl[p][1], bl[p][3]);
                MMA_BF16(acc + 32 + (2 * p) * 4,     a1, bl[p][0], bl[p][2]);
                MMA_BF16(acc + 32 + (2 * p + 1) * 4, a1, bl[p][1], bl[p][3]);
            }
        }
#pragma unroll
        for (int ks = 0; ks < 8; ks++) {
            const int ch = ks * 2 + lhalf;
            uint32_t a0[4], a1[4];
            ldm_x4(a0, aLo + ar0b + ((uint32_t)(ch ^ ar0x) << 4));
            ldm_x4(a1, aLo + ar1b + ((uint32_t)(ch ^ ar1x) << 4));
            uint32_t bh[4][4];
#pragma unroll
            for (int p = 0; p < 4; p++)
                ldm_x4(bh[p], wHi + brb[p] + ((uint32_t)(ch ^ brx[p]) << 4));
#pragma unroll
            for (int p = 0; p < 4; p++) {
                MMA_BF16(acc + (2 * p) * 4,      a0, bh[p][0], bh[p][2]);
                MMA_BF16(acc + (2 * p + 1) * 4,  a0, bh[p][1], bh[p][3]);
                MMA_BF16(acc + 32 + (2 * p) * 4,     a1, bh[p][0], bh[p][2]);
                MMA_BF16(acc + 32 + (2 * p + 1) * 4, a1, bh[p][1], bh[p][3]);
            }
        }
        __syncthreads();

        if (pass == 0) {
#pragma unroll
            for (int mt = 0; mt < 2; mt++) {
                int rbase = wm * 32 + mt * 16 + (lane >> 2);
#pragma unroll
                for (int h = 0; h < 2; h++) {
                    int rr = rbase + 8 * h;
                    int rb = rr * 256, rx = rr & 7;
#pragma unroll
                    for (int nt = 0; nt < 8; nt++) {
                        int c = wn * 64 + nt * 8 + 2 * (lane & 3);
                        int ai = mt * 32 + nt * 4 + 2 * h;
                        float v0 = fmaxf(fmaf(acc[ai],     s_sc1[c],     s_sh1[c]),     0.f);
                        float v1f = fmaxf(fmaf(acc[ai + 1], s_sc1[c + 1], s_sh1[c + 1]), 0.f);
                        uint32_t off = (uint32_t)(rb + (((c >> 3) ^ rx) << 4) + ((c & 7) << 1));
                        *reinterpret_cast<uint32_t*>(smc + SM_AHI + off) = pack_hi(v0, v1f);
                        *reinterpret_cast<uint32_t*>(smc + SM_ALO + off) = pack_lo(v0, v1f);
                    }
                }
            }
            {
                const uint4* sh = reinterpret_cast<const uint4*>(g_WT[layer][1][0]);
                const uint4* sl = reinterpret_cast<const uint4*>(g_WT[layer][1][1]);
                uint4* dh = reinterpret_cast<uint4*>(smc + SM_WHI);
                uint4* dl = reinterpret_cast<uint4*>(smc + SM_WLO);
#pragma unroll
                for (int i = 0; i < 8; i++) {
                    dh[tid + i * 256] = sh[tid + i * 256];
                    dl[tid + i * 256] = sl[tid + i * 256];
                }
            }
#pragma unroll
            for (int i = 0; i < 64; i++) acc[i] = 0.f;
            __syncthreads();
        }
    }

    // Epilogue 2: Xn = relu(bn2(acc)) -> g_X + g_XB16 + pool atomics
    float* poolbase = &g_POOL[(size_t)(layer + 1) * GG * DD];
#pragma unroll
    for (int mt = 0; mt < 2; mt++) {
#pragma unroll
        for (int h = 0; h < 2; h++) {
            int m = m0 + wm * 32 + mt * 16 + (lane >> 2) + 8 * h;
            if (m < NN) {
                int g = batch[m];
#pragma unroll
                for (int nt = 0; nt < 8; nt++) {
                    int c = wn * 64 + nt * 8 + 2 * (lane & 3);
                    int ai = mt * 32 + nt * 4 + 2 * h;
                    float v0 = fmaxf(fmaf(acc[ai],     s_sc2[c],     s_sh2[c]),     0.f);
                    float v1f = fmaxf(fmaf(acc[ai + 1], s_sc2[c + 1], s_sh2[c + 1]), 0.f);
                    *reinterpret_cast<float2*>(&g_X[(size_t)m * DD + c]) = make_float2(v0, v1f);
                    if (layer + 1 < LYR)
                        *reinterpret_cast<uint32_t*>(&g_XB16[(size_t)m * DD + c]) = pack_hi(v0, v1f);
                    red_add_v2(&poolbase[g * DD + c], v0, v1f);
                }
            }
        }
    }
}

// ---------------------------------------------------------------------------
__global__ void head_kernel(const float* __restrict__ fcw,
                            const float* __restrict__ fcb,
                            float* __restrict__ out) {
    __shared__ float s[OO * DD];
    const int g = blockIdx.x;
    const int d = threadIdx.x;
    const float inv = 1.0f / fmaxf(g_CNT[g], 1.0f);

    float acc[OO];
#pragma unroll
    for (int o = 0; o < OO; o++) acc[o] = 0.f;

    for (int i = 0; i < LYR + 1; i++) {
        float p = g_POOL[(size_t)i * GG * DD + g * DD + d] * inv;
        const float* wrow = &fcw[((size_t)i * DD + d) * OO];
#pragma unroll
        for (int o = 0; o < OO; o++) acc[o] = fmaf(p, wrow[o], acc[o]);
    }
#pragma unroll
    for (int o = 0; o < OO; o++) s[o * DD + d] = acc[o];

    for (int st = 64; st > 0; st >>= 1) {
        __syncthreads();
        if (d < st) {
#pragma unroll
            for (int o = 0; o < OO; o++) s[o * DD + d] += s[o * DD + d + st];
        }
    }
    __syncthreads();
    if (d < OO) {
        float b = 0.f;
        for (int i = 0; i < LYR + 1; i++) b += fcb[i * OO + d];
        out[g * OO + d] = s[d * DD] + b;
    }
}

// ---------------------------------------------------------------------------
extern "C" void kernel_launch(void* const* d_in, const int* in_sizes, int n_in,
                              void* d_out, int out_size) {
    const float* x     = (const float*)d_in[0];
    const int*   ei    = (const int*)d_in[1];
    const int*   eattr = (const int*)d_in[2];
    const int*   batch = (const int*)d_in[3];
    const float* bemb  = (const float*)d_in[4];
    const float* w1    = (const float*)d_in[5];
    const float* b1    = (const float*)d_in[6];
    const float* cbg   = (const float*)d_in[7];
    const float* cbb   = (const float*)d_in[8];
    const float* cbm   = (const float*)d_in[9];
    const float* cbv   = (const float*)d_in[10];
    const float* w2    = (const float*)d_in[11];
    const float* b2    = (const float*)d_in[12];
    const float* bg    = (const float*)d_in[13];
    const float* bb    = (const float*)d_in[14];
    const float* bm    = (const float*)d_in[15];
    const float* bv    = (const float*)d_in[16];
    const float* fcw   = (const float*)d_in[17];
    const float* fcb   = (const float*)d_in[18];
    float* out = (float*)d_out;

    const int gemm_grid = (NN + 127) / 128;           // 391
    const int pool_grid = (NN * 32 + 255) / 256;
    const int msg_grid = (NN + 7) / 8;

    cudaFuncSetAttribute(fused_mma_kernel,
                         cudaFuncAttributeMaxDynamicSharedMemorySize, SM_TOTAL);

    zero_pool_kernel<<<((LYR + 1) * GG * DD + 255) / 256, 256>>>();
    x2b16_kernel<<<(NN * DD / 2 + 255) / 256, 256>>>(x);
    pool0_kernel<<<pool_grid, 256>>>(x, batch);
    hist_kernel<<<(EE + 255) / 256, 256>>>(ei);
    combo_kernel<<<dim3(512, LYR), 128>>>(bemb);
    prep_w_kernel<<<dim3(LYR, 2, 4), 256>>>(w1, w2);
    scan_kernel<<<1, 1024>>>();
    scatter_kernel<<<(EE + 255) / 256, 256>>>(ei, eattr);

    for (int i = 0; i < LYR; i++) {
        const float* xin = (i == 0) ? x : nullptr;
        msg_csr_kernel<<<msg_grid, 256>>>(i);
        fused_mma_kernel<<<gemm_grid, 256, SM_TOTAL>>>(
            xin, batch,
            b1 + i * DD, cbg + i * DD, cbb + i * DD, cbm + i * DD, cbv + i * DD,
            b2 + i * DD, bg + i * DD, bb + i * DD, bm + i * DD, bv + i * DD,
            i);
    }
    head_kernel<<<GG, DD>>>(fcw, fcb, out);
}

// round 16
// speedup vs baseline: 1.6141x; 1.6141x over previous
#include <cuda_runtime.h>
#include <cuda_bf16.h>
#include <cstdint>

constexpr int LYR = 5;
constexpr int NN  = 50000;
constexpr int EE  = 600000;
constexpr int DD  = 128;
constexpr int GG  = 256;
constexpr int OO  = 10;
constexpr float BN_EPS = 1e-5f;

__device__ float g_X[NN * DD];
__device__ float g_AGGR[NN * DD];
__device__ float g_POOL[(LYR + 1) * GG * DD];
__device__ float g_CNT[GG];
__device__ __align__(16) __nv_bfloat16 g_COMBO[LYR * 512 * DD];
// CSR (rebuilt every launch; edges sorted by dst)
__device__ int  g_DEG[NN];
__device__ int  g_ROWPTR[NN + 1];
__device__ int  g_WPOS[NN];
__device__ __align__(16) int2 g_ESRC[EE];          // {src, combo_code}
// Pre-transposed, split, swizzled weights: [layer][w1/w2][hi/lo][n*128 + swizzled k]
__device__ __align__(16) __nv_bfloat16 g_WT[LYR][2][2][DD * DD];

// ---------------------------------------------------------------------------
// Helpers
// ---------------------------------------------------------------------------
__device__ __forceinline__ uint32_t smem_u32(const void* p) {
    uint32_t a;
    asm("{ .reg .u64 t; cvta.to.shared.u64 t, %1; cvt.u32.u64 %0, t; }" : "=r"(a) : "l"(p));
    return a;
}

__device__ __forceinline__ void red_add_v4(float* addr, float a, float b, float c, float d) {
    asm volatile(
        "{ .reg .u64 p; cvta.to.global.u64 p, %0;\n\t"
        "red.global.add.v4.f32 [p], {%1, %2, %3, %4}; }"
        :: "l"(addr), "f"(a), "f"(b), "f"(c), "f"(d) : "memory");
}
__device__ __forceinline__ void red_add_v2(float* addr, float a, float b) {
    asm volatile(
        "{ .reg .u64 p; cvta.to.global.u64 p, %0;\n\t"
        "red.global.add.v2.f32 [p], {%1, %2}; }"
        :: "l"(addr), "f"(a), "f"(b) : "memory");
}

__device__ __forceinline__ void ldm_x4(uint32_t* r, uint32_t addr) {
    asm volatile("ldmatrix.sync.aligned.m8n8.x4.shared.b16 {%0,%1,%2,%3}, [%4];"
        : "=r"(r[0]), "=r"(r[1]), "=r"(r[2]), "=r"(r[3]) : "r"(addr));
}

#define MMA_BF16(d, a, b0_, b1_) \
    asm volatile("mma.sync.aligned.m16n8k16.row.col.f32.bf16.bf16.f32 " \
        "{%0,%1,%2,%3}, {%4,%5,%6,%7}, {%8,%9}, {%0,%1,%2,%3};" \
        : "+f"((d)[0]), "+f"((d)[1]), "+f"((d)[2]), "+f"((d)[3]) \
        : "r"((a)[0]), "r"((a)[1]), "r"((a)[2]), "r"((a)[3]), "r"(b0_), "r"(b1_))

__device__ __forceinline__ uint32_t pack_hi(float v0, float v1) {
    __nv_bfloat16 h0 = __float2bfloat16(v0), h1 = __float2bfloat16(v1);
    return (uint32_t)__bfloat16_as_ushort(h0) | ((uint32_t)__bfloat16_as_ushort(h1) << 16);
}
__device__ __forceinline__ uint32_t pack_lo(float v0, float v1) {
    __nv_bfloat16 h0 = __float2bfloat16(v0), h1 = __float2bfloat16(v1);
    __nv_bfloat16 l0 = __float2bfloat16(v0 - __bfloat162float(h0));
    __nv_bfloat16 l1 = __float2bfloat16(v1 - __bfloat162float(h1));
    return (uint32_t)__bfloat16_as_ushort(l0) | ((uint32_t)__bfloat16_as_ushort(l1) << 16);
}

// XOR-swizzled byte offset in a 128x128 bf16 tile (rows of 256B, 16B chunks)
__device__ __forceinline__ uint32_t sw_off(int row, int chunk) {
    return (uint32_t)(row * 256 + ((chunk ^ (row & 7)) << 4));
}

// SMEM layout (bytes) — 128-row tile (R9 layout)
constexpr int SM_SC1 = 0;
constexpr int SM_SH1 = 512;
constexpr int SM_SC2 = 1024;
constexpr int SM_SH2 = 1536;
constexpr int SM_AHI = 2048;
constexpr int SM_ALO = SM_AHI + 32768;
constexpr int SM_WHI = SM_ALO + 32768;
constexpr int SM_WLO = SM_WHI + 32768;
constexpr int SM_TOTAL = SM_WLO + 32768;     // 133120 B

// ---------------------------------------------------------------------------
// Setup kernels
// ---------------------------------------------------------------------------
__global__ void zero_pool_kernel() {
    int idx = blockIdx.x * blockDim.x + threadIdx.x;
    if (idx < (LYR + 1) * GG * DD) g_POOL[idx] = 0.f;
    if (idx < GG) g_CNT[idx] = 0.f;
    if (idx < NN) g_DEG[idx] = 0;
}

__global__ void pool0_kernel(const float* __restrict__ x, const int* __restrict__ batch) {
    int idx = blockIdx.x * blockDim.x + threadIdx.x;
    int n = idx >> 5;
    int lane = idx & 31;
    if (n >= NN) return;
    int g = batch[n];
    if (lane == 0) atomicAdd(&g_CNT[g], 1.0f);
    float4 v = *reinterpret_cast<const float4*>(&x[n * DD + lane * 4]);
    red_add_v4(&g_POOL[g * DD + lane * 4], v.x, v.y, v.z, v.w);
}

__global__ void hist_kernel(const int* __restrict__ ei) {
    int e = blockIdx.x * blockDim.x + threadIdx.x;
    if (e < EE) atomicAdd(&g_DEG[ei[EE + e]], 1);
}

__global__ void scan_kernel() {
    __shared__ int part[1024];
    const int t = threadIdx.x;
    const int CH = (NN + 1023) / 1024;
    const int base = t * CH;
    int sum = 0;
    for (int j = 0; j < CH; j++) {
        int i = base + j;
        if (i < NN) sum += g_DEG[i];
    }
    part[t] = sum;
    __syncthreads();
    for (int off = 1; off < 1024; off <<= 1) {
        int v = (t >= off) ? part[t - off] : 0;
        __syncthreads();
        part[t] += v;
        __syncthreads();
    }
    int run = (t == 0) ? 0 : part[t - 1];
    for (int j = 0; j < CH; j++) {
        int i = base + j;
        if (i < NN) {
            g_ROWPTR[i] = run;
            g_WPOS[i] = run;
            run += g_DEG[i];
        }
    }
    if (t == 1023) g_ROWPTR[NN] = run;
}

__global__ void scatter_kernel(const int* __restrict__ ei, const int* __restrict__ eattr) {
    int e = blockIdx.x * blockDim.x + threadIdx.x;
    if (e < EE) {
        int dst = ei[EE + e];
        int pos = atomicAdd(&g_WPOS[dst], 1);
        int2 rec;
        rec.x = ei[e];
        rec.y = eattr[e * 3 + 0] + 8 * eattr[e * 3 + 1] + 64 * eattr[e * 3 + 2];
        g_ESRC[pos] = rec;
    }
}

// All-layer combined bond tables (bf16): grid (512, LYR)
__global__ void combo_kernel(const float* __restrict__ bemb) {
    int c = blockIdx.x, l = blockIdx.y, d = threadIdx.x;
    const float* bl = bemb + (size_t)l * 3 * 8 * DD;
    int a0 = c & 7, a1 = (c >> 3) & 7, a2 = c >> 6;
    float s = bl[a0 * DD + d] + bl[(8 + a1) * DD + d] + bl[(16 + a2) * DD + d];
    g_COMBO[((size_t)l * 512 + c) * DD + d] = __float2bfloat16(s);
}

// Transpose + split + swizzle weights: grid (LYR, 2, 4)
__global__ void prep_w_kernel(const float* __restrict__ w1, const float* __restrict__ w2) {
    int l = blockIdx.x, which = blockIdx.y, part = blockIdx.z;
    const float* W = (which ? w2 : w1) + (size_t)l * DD * DD;
    __nv_bfloat16* dst_hi = g_WT[l][which][0];
    __nv_bfloat16* dst_lo = g_WT[l][which][1];
    const int quarter = DD * DD / 4;
    for (int idx = part * quarter + threadIdx.x; idx < (part + 1) * quarter; idx += blockDim.x) {
        int k = idx >> 7, n = idx & 127;
        float v = W[idx];
        __nv_bfloat16 hi = __float2bfloat16(v);
        __nv_bfloat16 lo = __float2bfloat16(v - __bfloat162float(hi));
        int sidx = n * DD + (((k >> 3) ^ (n & 7)) << 3) + (k & 7);
        dst_hi[sidx] = hi;
        dst_lo[sidx] = lo;
    }
}

// ---------------------------------------------------------------------------
// CSR gather aggregation: AGGR[n] = sum over in-edges relu(x[src] + combo)
// One warp per node; 2-edge software pipelining for MLP; plain store.
// ---------------------------------------------------------------------------
__global__ void __launch_bounds__(256)
msg_csr_kernel(const float* __restrict__ xext, int layer) {
    const float* xp = xext ? xext : g_X;
    const __nv_bfloat16* combo = g_COMBO + (size_t)layer * 512 * DD;
    const int lane = threadIdx.x & 31;
    const int n = blockIdx.x * 8 + (threadIdx.x >> 5);
    if (n >= NN) return;

    const int s = g_ROWPTR[n];
    const int e = g_ROWPTR[n + 1];
    float4 acc = make_float4(0.f, 0.f, 0.f, 0.f);

    int i = s;
    for (; i + 1 < e; i += 2) {
        int2 ed0 = g_ESRC[i];
        int2 ed1 = g_ESRC[i + 1];
        uint2 cu0 = *reinterpret_cast<const uint2*>(&combo[(size_t)ed0.y * DD + lane * 4]);
        float4 xv0 = *reinterpret_cast<const float4*>(&xp[(size_t)ed0.x * DD + lane * 4]);
        uint2 cu1 = *reinterpret_cast<const uint2*>(&combo[(size_t)ed1.y * DD + lane * 4]);
        float4 xv1 = *reinterpret_cast<const float4*>(&xp[(size_t)ed1.x * DD + lane * 4]);
        float2 c00 = __bfloat1622float2(*reinterpret_cast<__nv_bfloat162*>(&cu0.x));
        float2 c01 = __bfloat1622float2(*reinterpret_cast<__nv_bfloat162*>(&cu0.y));
        float2 c10 = __bfloat1622float2(*reinterpret_cast<__nv_bfloat162*>(&cu1.x));
        float2 c11 = __bfloat1622float2(*reinterpret_cast<__nv_bfloat162*>(&cu1.y));
        acc.x += fmaxf(xv0.x + c00.x, 0.f) + fmaxf(xv1.x + c10.x, 0.f);
        acc.y += fmaxf(xv0.y + c00.y, 0.f) + fmaxf(xv1.y + c10.y, 0.f);
        acc.z += fmaxf(xv0.z + c01.x, 0.f) + fmaxf(xv1.z + c11.x, 0.f);
        acc.w += fmaxf(xv0.w + c01.y, 0.f) + fmaxf(xv1.w + c11.y, 0.f);
    }
    if (i < e) {
        int2 ed = g_ESRC[i];
        uint2 cu = *reinterpret_cast<const uint2*>(&combo[(size_t)ed.y * DD + lane * 4]);
        float4 xv = *reinterpret_cast<const float4*>(&xp[(size_t)ed.x * DD + lane * 4]);
        float2 c0 = __bfloat1622float2(*reinterpret_cast<__nv_bfloat162*>(&cu.x));
        float2 c1 = __bfloat1622float2(*reinterpret_cast<__nv_bfloat162*>(&cu.y));
        acc.x += fmaxf(xv.x + c0.x, 0.f);
        acc.y += fmaxf(xv.y + c0.y, 0.f);
        acc.z += fmaxf(xv.z + c1.x, 0.f);
        acc.w += fmaxf(xv.w + c1.y, 0.f);
    }
    *reinterpret_cast<float4*>(&g_AGGR[(size_t)n * DD + lane * 4]) = acc;
}

// ---------------------------------------------------------------------------
// Fused layer kernel (HMMA bf16 split-3x), 128-row tile — exact R9 version
// ---------------------------------------------------------------------------
__global__ void __launch_bounds__(256)
fused_mma_kernel(const float* __restrict__ xext,
                 const int* __restrict__ batch,
                 const float* __restrict__ b1,
                 const float* __restrict__ g1, const float* __restrict__ be1,
                 const float* __restrict__ mu1, const float* __restrict__ v1,
                 const float* __restrict__ b2,
                 const float* __restrict__ g2, const float* __restrict__ be2,
                 const float* __restrict__ mu2, const float* __restrict__ v2,
                 int layer) {
    extern __shared__ char smc[];
    const int tid = threadIdx.x;
    const int lane = tid & 31;
    const int wid = tid >> 5;
    const int wm = wid >> 1;
    const int wn = wid & 1;
    const int m0 = blockIdx.x * 128;
    const float* Ain = xext ? xext : g_X;

    float* s_sc1 = reinterpret_cast<float*>(smc + SM_SC1);
    float* s_sh1 = reinterpret_cast<float*>(smc + SM_SH1);
    float* s_sc2 = reinterpret_cast<float*>(smc + SM_SC2);
    float* s_sh2 = reinterpret_cast<float*>(smc + SM_SH2);

    const uint32_t aHi = smem_u32(smc + SM_AHI);
    const uint32_t aLo = smem_u32(smc + SM_ALO);
    const uint32_t wHi = smem_u32(smc + SM_WHI);
    const uint32_t wLo = smem_u32(smc + SM_WLO);

    if (tid < 128) {
        int c = tid;
        float s1 = g1[c] * rsqrtf(v1[c] + BN_EPS);
        s_sc1[c] = s1;
        s_sh1[c] = be1[c] + (b1[c] - mu1[c]) * s1;
        float s2 = g2[c] * rsqrtf(v2[c] + BN_EPS);
        s_sc2[c] = s2;
        s_sh2[c] = be2[c] + (b2[c] - mu2[c]) * s2;
    }
    {
        const int r = tid >> 1;
        const int h = tid & 1;
        const int m = m0 + r;
#pragma unroll
        for (int q = 0; q < 8; q++) {
            int c0 = h * 64 + q * 8;
            float4 v0 = make_float4(0.f, 0.f, 0.f, 0.f);
            float4 v1f = make_float4(0.f, 0.f, 0.f, 0.f);
            if (m < NN) {
                size_t gi = (size_t)m * DD + c0;
                v0 = *reinterpret_cast<const float4*>(&Ain[gi]);
                v1f = *reinterpret_cast<const float4*>(&Ain[gi + 4]);
                float4 a0 = *reinterpret_cast<const float4*>(&g_AGGR[gi]);
                float4 a1 = *reinterpret_cast<const float4*>(&g_AGGR[gi + 4]);
                v0.x += a0.x; v0.y += a0.y; v0.z += a0.z; v0.w += a0.w;
                v1f.x += a1.x; v1f.y += a1.y; v1f.z += a1.z; v1f.w += a1.w;
            }
            uint32_t off = sw_off(r, h * 8 + q);
            uint4 hi4 = make_uint4(pack_hi(v0.x, v0.y), pack_hi(v0.z, v0.w),
                                   pack_hi(v1f.x, v1f.y), pack_hi(v1f.z, v1f.w));
            uint4 lo4 = make_uint4(pack_lo(v0.x, v0.y), pack_lo(v0.z, v0.w),
                                   pack_lo(v1f.x, v1f.y), pack_lo(v1f.z, v1f.w));
            *reinterpret_cast<uint4*>(smc + SM_AHI + off) = hi4;
            *reinterpret_cast<uint4*>(smc + SM_ALO + off) = lo4;
        }
    }
    {
        const uint4* sh = reinterpret_cast<const uint4*>(g_WT[layer][0][0]);
        const uint4* sl = reinterpret_cast<const uint4*>(g_WT[layer][0][1]);
        uint4* dh = reinterpret_cast<uint4*>(smc + SM_WHI);
        uint4* dl = reinterpret_cast<uint4*>(smc + SM_WLO);
#pragma unroll
        for (int i = 0; i < 8; i++) {
            dh[tid + i * 256] = sh[tid + i * 256];
            dl[tid + i * 256] = sl[tid + i * 256];
        }
    }
    __syncthreads();

    const int lrow = lane & 15;
    const int lhalf = lane >> 4;
    const int ar0 = wm * 32 + lrow;
    const int ar1 = ar0 + 16;
    const int ar0b = ar0 * 256, ar0x = ar0 & 7;
    const int ar1b = ar1 * 256, ar1x = ar1 & 7;
    int brb[4], brx[4];
#pragma unroll
    for (int p = 0; p < 4; p++) {
        int nr = wn * 64 + p * 16 + lrow;
        brb[p] = nr * 256;
        brx[p] = nr & 7;
    }

    float acc[64];
#pragma unroll
    for (int i = 0; i < 64; i++) acc[i] = 0.f;

    for (int pass = 0; pass < 2; ++pass) {
#pragma unroll
        for (int ks = 0; ks < 8; ks++) {
            const int ch = ks * 2 + lhalf;
            uint32_t a0[4], a1[4];
            ldm_x4(a0, aHi + ar0b + ((uint32_t)(ch ^ ar0x) << 4));
            ldm_x4(a1, aHi + ar1b + ((uint32_t)(ch ^ ar1x) << 4));
            uint32_t bh[4][4], bl[4][4];
#pragma unroll
            for (int p = 0; p < 4; p++) {
                uint32_t o = (uint32_t)(ch ^ brx[p]) << 4;
                ldm_x4(bh[p], wHi + brb[p] + o);
                ldm_x4(bl[p], wLo + brb[p] + o);
            }
#pragma unroll
            for (int p = 0; p < 4; p++) {
                MMA_BF16(acc + (2 * p) * 4,      a0, bh[p][0], bh[p][2]);
                MMA_BF16(acc + (2 * p + 1) * 4,  a0, bh[p][1], bh[p][3]);
                MMA_BF16(acc + 32 + (2 * p) * 4,     a1, bh[p][0], bh[p][2]);
                MMA_BF16(acc + 32 + (2 * p + 1) * 4, a1, bh[p][1], bh[p][3]);
                MMA_BF16(acc + (2 * p) * 4,      a0, bl[p][0], bl[p][2]);
                MMA_BF16(acc + (2 * p + 1) * 4,  a0, bl[p][1], bl[p][3]);
                MMA_BF16(acc + 32 + (2 * p) * 4,     a1, bl[p][0], bl[p][2]);
                MMA_BF16(acc + 32 + (2 * p + 1) * 4, a1, bl[p][1], bl[p][3]);
            }
        }
#pragma unroll
        for (int ks = 0; ks < 8; ks++) {
            const int ch = ks * 2 + lhalf;
            uint32_t a0[4], a1[4];
            ldm_x4(a0, aLo + ar0b + ((uint32_t)(ch ^ ar0x) << 4));
            ldm_x4(a1, aLo + ar1b + ((uint32_t)(ch ^ ar1x) << 4));
            uint32_t bh[4][4];
#pragma unroll
            for (int p = 0; p < 4; p++)
                ldm_x4(bh[p], wHi + brb[p] + ((uint32_t)(ch ^ brx[p]) << 4));
#pragma unroll
            for (int p = 0; p < 4; p++) {
                MMA_BF16(acc + (2 * p) * 4,      a0, bh[p][0], bh[p][2]);
                MMA_BF16(acc + (2 * p + 1) * 4,  a0, bh[p][1], bh[p][3]);
                MMA_BF16(acc + 32 + (2 * p) * 4,     a1, bh[p][0], bh[p][2]);
                MMA_BF16(acc + 32 + (2 * p + 1) * 4, a1, bh[p][1], bh[p][3]);
            }
        }
        __syncthreads();

        if (pass == 0) {
#pragma unroll
            for (int mt = 0; mt < 2; mt++) {
                int rbase = wm * 32 + mt * 16 + (lane >> 2);
#pragma unroll
                for (int h = 0; h < 2; h++) {
                    int rr = rbase + 8 * h;
                    int rb = rr * 256, rx = rr & 7;
#pragma unroll
                    for (int nt = 0; nt < 8; nt++) {
                        int c = wn * 64 + nt * 8 + 2 * (lane & 3);
                        int ai = mt * 32 + nt * 4 + 2 * h;
                        float v0 = fmaxf(fmaf(acc[ai],     s_sc1[c],     s_sh1[c]),     0.f);
                        float v1f = fmaxf(fmaf(acc[ai + 1], s_sc1[c + 1], s_sh1[c + 1]), 0.f);
                        uint32_t off = (uint32_t)(rb + (((c >> 3) ^ rx) << 4) + ((c & 7) << 1));
                        *reinterpret_cast<uint32_t*>(smc + SM_AHI + off) = pack_hi(v0, v1f);
                        *reinterpret_cast<uint32_t*>(smc + SM_ALO + off) = pack_lo(v0, v1f);
                    }
                }
            }
            {
                const uint4* sh = reinterpret_cast<const uint4*>(g_WT[layer][1][0]);
                const uint4* sl = reinterpret_cast<const uint4*>(g_WT[layer][1][1]);
                uint4* dh = reinterpret_cast<uint4*>(smc + SM_WHI);
                uint4* dl = reinterpret_cast<uint4*>(smc + SM_WLO);
#pragma unroll
                for (int i = 0; i < 8; i++) {
                    dh[tid + i * 256] = sh[tid + i * 256];
                    dl[tid + i * 256] = sl[tid + i * 256];
                }
            }
#pragma unroll
            for (int i = 0; i < 64; i++) acc[i] = 0.f;
            __syncthreads();
        }
    }

    float* poolbase = &g_POOL[(size_t)(layer + 1) * GG * DD];
#pragma unroll
    for (int mt = 0; mt < 2; mt++) {
#pragma unroll
        for (int h = 0; h < 2; h++) {
            int m = m0 + wm * 32 + mt * 16 + (lane >> 2) + 8 * h;
            if (m < NN) {
                int g = batch[m];
#pragma unroll
                for (int nt = 0; nt < 8; nt++) {
                    int c = wn * 64 + nt * 8 + 2 * (lane & 3);
                    int ai = mt * 32 + nt * 4 + 2 * h;
                    float v0 = fmaxf(fmaf(acc[ai],     s_sc2[c],     s_sh2[c]),     0.f);
                    float v1f = fmaxf(fmaf(acc[ai + 1], s_sc2[c + 1], s_sh2[c + 1]), 0.f);
                    *reinterpret_cast<float2*>(&g_X[(size_t)m * DD + c]) = make_float2(v0, v1f);
                    red_add_v2(&poolbase[g * DD + c], v0, v1f);
                }
            }
        }
    }
}

// ---------------------------------------------------------------------------
__global__ void head_kernel(const float* __restrict__ fcw,
                            const float* __restrict__ fcb,
                            float* __restrict__ out) {
    __shared__ float s[OO * DD];
    const int g = blockIdx.x;
    const int d = threadIdx.x;
    const float inv = 1.0f / fmaxf(g_CNT[g], 1.0f);

    float acc[OO];
#pragma unroll
    for (int o = 0; o < OO; o++) acc[o] = 0.f;

    for (int i = 0; i < LYR + 1; i++) {
        float p = g_POOL[(size_t)i * GG * DD + g * DD + d] * inv;
        const float* wrow = &fcw[((size_t)i * DD + d) * OO];
#pragma unroll
        for (int o = 0; o < OO; o++) acc[o] = fmaf(p, wrow[o], acc[o]);
    }
#pragma unroll
    for (int o = 0; o < OO; o++) s[o * DD + d] = acc[o];

    for (int st = 64; st > 0; st >>= 1) {
        __syncthreads();
        if (d < st) {
#pragma unroll
            for (int o = 0; o < OO; o++) s[o * DD + d] += s[o * DD + d + st];
        }
    }
    __syncthreads();
    if (d < OO) {
        float b = 0.f;
        for (int i = 0; i < LYR + 1; i++) b += fcb[i * OO + d];
        out[g * OO + d] = s[d * DD] + b;
    }
}

// ---------------------------------------------------------------------------
extern "C" void kernel_launch(void* const* d_in, const int* in_sizes, int n_in,
                              void* d_out, int out_size) {
    const float* x     = (const float*)d_in[0];
    const int*   ei    = (const int*)d_in[1];
    const int*   eattr = (const int*)d_in[2];
    const int*   batch = (const int*)d_in[3];
    const float* bemb  = (const float*)d_in[4];
    const float* w1    = (const float*)d_in[5];
    const float* b1    = (const float*)d_in[6];
    const float* cbg   = (const float*)d_in[7];
    const float* cbb   = (const float*)d_in[8];
    const float* cbm   = (const float*)d_in[9];
    const float* cbv   = (const float*)d_in[10];
    const float* w2    = (const float*)d_in[11];
    const float* b2    = (const float*)d_in[12];
    const float* bg    = (const float*)d_in[13];
    const float* bb    = (const float*)d_in[14];
    const float* bm    = (const float*)d_in[15];
    const float* bv    = (const float*)d_in[16];
    const float* fcw   = (const float*)d_in[17];
    const float* fcb   = (const float*)d_in[18];
    float* out = (float*)d_out;

    const int gemm_grid = (NN + 127) / 128;           // 391
    const int pool_grid = (NN * 32 + 255) / 256;
    const int msg_grid = (NN + 7) / 8;

    cudaFuncSetAttribute(fused_mma_kernel,
                         cudaFuncAttributeMaxDynamicSharedMemorySize, SM_TOTAL);

    zero_pool_kernel<<<((LYR + 1) * GG * DD + 255) / 256, 256>>>();
    pool0_kernel<<<pool_grid, 256>>>(x, batch);
    hist_kernel<<<(EE + 255) / 256, 256>>>(ei);
    combo_kernel<<<dim3(512, LYR), 128>>>(bemb);
    prep_w_kernel<<<dim3(LYR, 2, 4), 256>>>(w1, w2);
    scan_kernel<<<1, 1024>>>();
    scatter_kernel<<<(EE + 255) / 256, 256>>>(ei, eattr);

    for (int i = 0; i < LYR; i++) {
        const float* xin = (i == 0) ? x : nullptr;
        msg_csr_kernel<<<msg_grid, 256>>>(xin, i);
        fused_mma_kernel<<<gemm_grid, 256, SM_TOTAL>>>(
            xin, batch,
            b1 + i * DD, cbg + i * DD, cbb + i * DD, cbm + i * DD, cbv + i * DD,
            b2 + i * DD, bg + i * DD, bb + i * DD, bm + i * DD, bv + i * DD,
            i);
    }
    head_kernel<<<GG, DD>>>(fcw, fcb, out);
}